// round 2
// baseline (speedup 1.0000x reference)
#include <cuda_runtime.h>
#include <cstdint>

#define N_NODES 100000
#define N_EDGES 1600000
#define DIN     128
#define NH      4
#define DH      16
#define HD      64

// ---------------- scratch (static __device__ — no allocation allowed) ----------------
__device__ float g_h[(size_t)N_NODES * HD];       // transformed node features [N, 64]
__device__ float g_asrc[N_NODES * NH];            // <h[n,h,:], W_att[h, 0:16]>
__device__ float g_adst[N_NODES * NH];            // <h[n,h,:], W_att[h,16:32]>
__device__ float g_denom[N_NODES * NH];           // segment sum of exp(logit)
__device__ int   g_is64;                          // edge_index dtype flag

// ---------------- pass 0: zero out/denom, detect edge_index dtype ----------------
__global__ __launch_bounds__(256) void zero_detect_kernel(float* __restrict__ out,
                                                          const int* __restrict__ ei_words) {
    int t = blockIdx.x * blockDim.x + threadIdx.x;
    if (t < N_NODES * (HD / 4)) {
        reinterpret_cast<float4*>(out)[t] = make_float4(0.f, 0.f, 0.f, 0.f);
    }
    if (t < N_NODES * NH) g_denom[t] = 0.f;
    if (t == 0) {
        // int64 values < 2^31 => every odd 32-bit word is 0. For int32 data these
        // words are independent random indices; P(7 of them all zero) ~ 1e-35.
        int orw = ei_words[1] | ei_words[3] | ei_words[5] | ei_words[7]
                | ei_words[9] | ei_words[11] | ei_words[13];
        g_is64 = (orw == 0) ? 1 : 0;
    }
}

// ---------------- pass 1: node transform + attention partials ----------------
// One warp per node; 8 warps/block, 4 nodes per warp (32 nodes/block).
__global__ __launch_bounds__(256) void node_kernel(const float* __restrict__ x,
                                                   const float* __restrict__ W_lin,
                                                   const float* __restrict__ W_att) {
    __shared__ float sW[DIN * HD];    // 32 KB
    __shared__ float sx[8][DIN];      // 4 KB
    __shared__ float sWa[NH * 2 * DH];

    int tid = threadIdx.x;
    for (int i = tid; i < DIN * HD; i += 256) sW[i] = W_lin[i];
    if (tid < NH * 2 * DH) sWa[tid] = W_att[tid];
    __syncthreads();

    int warp = tid >> 5, lane = tid & 31;
    int c0 = lane, c1 = lane + 32;
    int head0 = lane >> 4;          // 0 or 1
    int head1 = head0 + 2;          // 2 or 3
    int kk = lane & 15;

    for (int iter = 0; iter < 4; iter++) {
        int n = (blockIdx.x * 4 + iter) * 8 + warp;   // grid covers exactly N
        float4 v = reinterpret_cast<const float4*>(x + (size_t)n * DIN)[lane];
        sx[warp][lane * 4 + 0] = v.x;
        sx[warp][lane * 4 + 1] = v.y;
        sx[warp][lane * 4 + 2] = v.z;
        sx[warp][lane * 4 + 3] = v.w;
        __syncwarp();

        float acc0 = 0.f, acc1 = 0.f;
        #pragma unroll 16
        for (int k = 0; k < DIN; k++) {
            float xv = sx[warp][k];
            acc0 += xv * sW[k * HD + c0];
            acc1 += xv * sW[k * HD + c1];
        }
        g_h[(size_t)n * HD + c0] = acc0;
        g_h[(size_t)n * HD + c1] = acc1;

        // attention partials: a_src[n,h] = sum_k h[n, h*16+k] * W_att[h, k]
        float ps0 = acc0 * sWa[head0 * 32 + kk];
        float pd0 = acc0 * sWa[head0 * 32 + 16 + kk];
        float ps1 = acc1 * sWa[head1 * 32 + kk];
        float pd1 = acc1 * sWa[head1 * 32 + 16 + kk];
        #pragma unroll
        for (int off = 8; off; off >>= 1) {
            ps0 += __shfl_xor_sync(0xffffffffu, ps0, off);
            pd0 += __shfl_xor_sync(0xffffffffu, pd0, off);
            ps1 += __shfl_xor_sync(0xffffffffu, ps1, off);
            pd1 += __shfl_xor_sync(0xffffffffu, pd1, off);
        }
        if (kk == 0) {
            g_asrc[n * NH + head0] = ps0;
            g_adst[n * NH + head0] = pd0;
            g_asrc[n * NH + head1] = ps1;
            g_adst[n * NH + head1] = pd1;
        }
        __syncwarp();
    }
}

// ---------------- pass 2: edge scatter ----------------
// 16 threads per edge: thread sub = h*4 + q handles float4 chunk q of head h.
// Logit computed once per (edge, head) by the q==0 thread, broadcast via shfl.
__global__ __launch_bounds__(256) void edge_kernel(const void* __restrict__ ei,
                                                   float* __restrict__ out) {
    int t = blockIdx.x * blockDim.x + threadIdx.x;
    int e = t >> 4;
    if (e >= N_EDGES) return;
    int sub = t & 15;
    int hh = sub >> 2, q = sub & 3;

    long long s, d;
    if (g_is64) {
        const long long* p = (const long long*)ei;
        s = __ldg(p + e);
        d = __ldg(p + N_EDGES + e);
    } else {
        const int* p = (const int*)ei;
        s = __ldg(p + e);
        d = __ldg(p + N_EDGES + e);
    }

    float ex;
    if (q == 0) {
        float lg = __ldg(&g_asrc[s * NH + hh]) + __ldg(&g_adst[d * NH + hh]);
        lg = lg > 0.f ? lg : 0.2f * lg;              // leaky_relu(0.2)
        ex = __expf(lg);                             // no max-shift: |lg| <~ 1.5
    }
    // broadcast from the q==0 lane of this (edge, head) group (lanes share warp)
    int src_lane = (threadIdx.x & 31) & ~3;
    ex = __shfl_sync(0xffffffffu, ex, src_lane);

    float4 v = __ldg(reinterpret_cast<const float4*>(&g_h[d * HD + hh * DH + q * 4]));
    float4 m = make_float4(ex * v.x, ex * v.y, ex * v.z, ex * v.w);

    float* dst = out + s * HD + hh * DH + q * 4;
    asm volatile("red.global.add.v4.f32 [%0], {%1,%2,%3,%4};"
                 :: "l"(dst), "f"(m.x), "f"(m.y), "f"(m.z), "f"(m.w) : "memory");
    if (q == 0) atomicAdd(&g_denom[s * NH + hh], ex);
}

// ---------------- pass 3: normalize ----------------
__global__ __launch_bounds__(256) void norm_kernel(float* __restrict__ out) {
    int t = blockIdx.x * blockDim.x + threadIdx.x;   // one float4 per thread
    if (t >= N_NODES * (HD / 4)) return;
    int n = t >> 4;
    int hh = (t >> 2) & 3;
    float inv = 1.f / (g_denom[n * NH + hh] + 1e-16f);
    float4 v = reinterpret_cast<float4*>(out)[t];
    v.x *= inv; v.y *= inv; v.z *= inv; v.w *= inv;
    reinterpret_cast<float4*>(out)[t] = v;
}

// ---------------- launch ----------------
extern "C" void kernel_launch(void* const* d_in, const int* in_sizes, int n_in,
                              void* d_out, int out_size) {
    const float* x     = (const float*)d_in[0];
    const void*  ei    = d_in[1];
    const float* W_lin = (const float*)d_in[2];
    const float* W_att = (const float*)d_in[3];
    float* out = (float*)d_out;

    int zthreads = N_NODES * (HD / 4);                       // 1.6M
    zero_detect_kernel<<<(zthreads + 255) / 256, 256>>>(out, (const int*)ei);

    node_kernel<<<N_NODES / 32, 256>>>(x, W_lin, W_att);     // 3125 blocks

    int ethreads = N_EDGES * 16;                             // 25.6M
    edge_kernel<<<(ethreads + 255) / 256, 256>>>(ei, out);

    norm_kernel<<<(zthreads + 255) / 256, 256>>>(out);
}

// round 3
// speedup vs baseline: 1.1652x; 1.1652x over previous
#include <cuda_runtime.h>
#include <cstdint>

#define N_NODES 100000
#define N_EDGES 1600000
#define DIN     128
#define NH      4
#define DH      16
#define HD      64

#define SCAN_BLK   1024
#define SCAN_NBLK  98          // 98*1024 = 100352 >= N_NODES

// ---------------- scratch (static __device__ — no allocation) ----------------
__device__ float g_h[(size_t)N_NODES * HD];     // transformed node features [N,64]
__device__ float g_asrc[N_NODES * NH];          // <h[n,h,:], W_att[h, 0:16]>
__device__ float g_adst[N_NODES * NH];          // <h[n,h,:], W_att[h,16:32]>
__device__ int   g_cnt[SCAN_NBLK * SCAN_BLK];   // per-source edge counts (padded)
__device__ int   g_start[N_NODES + 1];          // CSR row offsets
__device__ int   g_cursor[N_NODES];             // scatter cursors
__device__ int   g_bsum[SCAN_NBLK];             // block sums for scan
__device__ int   g_dst[N_EDGES];                // CSR column indices (d per edge)
__device__ int   g_is64;                        // edge_index dtype flag

// ---------------- pass 0: zero counts, detect edge dtype ----------------
__global__ __launch_bounds__(256) void pass0_kernel(const int* __restrict__ ei_words) {
    int t = blockIdx.x * blockDim.x + threadIdx.x;
    if (t < SCAN_NBLK * SCAN_BLK) g_cnt[t] = 0;
    if (t == 0) {
        // int64 values < 2^31 => odd 32-bit words are all zero; for int32 data
        // these words are random indices (P(all zero) ~ 1e-35).
        int orw = ei_words[1] | ei_words[3] | ei_words[5] | ei_words[7]
                | ei_words[9] | ei_words[11] | ei_words[13];
        g_is64 = (orw == 0) ? 1 : 0;
    }
}

// ---------------- pass 1: node transform + attention partials ----------------
__global__ __launch_bounds__(256) void node_kernel(const float* __restrict__ x,
                                                   const float* __restrict__ W_lin,
                                                   const float* __restrict__ W_att) {
    __shared__ float sW[DIN * HD];
    __shared__ float sx[8][DIN];
    __shared__ float sWa[NH * 2 * DH];

    int tid = threadIdx.x;
    for (int i = tid; i < DIN * HD; i += 256) sW[i] = W_lin[i];
    if (tid < NH * 2 * DH) sWa[tid] = W_att[tid];
    __syncthreads();

    int warp = tid >> 5, lane = tid & 31;
    int c0 = lane, c1 = lane + 32;
    int head0 = lane >> 4;          // 0 or 1
    int head1 = head0 + 2;          // 2 or 3
    int kk = lane & 15;

    for (int iter = 0; iter < 4; iter++) {
        int n = (blockIdx.x * 4 + iter) * 8 + warp;   // exactly covers N
        float4 v = reinterpret_cast<const float4*>(x + (size_t)n * DIN)[lane];
        sx[warp][lane * 4 + 0] = v.x;
        sx[warp][lane * 4 + 1] = v.y;
        sx[warp][lane * 4 + 2] = v.z;
        sx[warp][lane * 4 + 3] = v.w;
        __syncwarp();

        float acc0 = 0.f, acc1 = 0.f;
        #pragma unroll 16
        for (int k = 0; k < DIN; k++) {
            float xv = sx[warp][k];
            acc0 += xv * sW[k * HD + c0];
            acc1 += xv * sW[k * HD + c1];
        }
        g_h[(size_t)n * HD + c0] = acc0;
        g_h[(size_t)n * HD + c1] = acc1;

        float ps0 = acc0 * sWa[head0 * 32 + kk];
        float pd0 = acc0 * sWa[head0 * 32 + 16 + kk];
        float ps1 = acc1 * sWa[head1 * 32 + kk];
        float pd1 = acc1 * sWa[head1 * 32 + 16 + kk];
        #pragma unroll
        for (int off = 8; off; off >>= 1) {
            ps0 += __shfl_xor_sync(0xffffffffu, ps0, off);
            pd0 += __shfl_xor_sync(0xffffffffu, pd0, off);
            ps1 += __shfl_xor_sync(0xffffffffu, ps1, off);
            pd1 += __shfl_xor_sync(0xffffffffu, pd1, off);
        }
        if (kk == 0) {
            g_asrc[n * NH + head0] = ps0;
            g_adst[n * NH + head0] = pd0;
            g_asrc[n * NH + head1] = ps1;
            g_adst[n * NH + head1] = pd1;
        }
        __syncwarp();
    }
}

// ---------------- pass 2: histogram edges by source ----------------
__global__ __launch_bounds__(256) void count_kernel(const void* __restrict__ ei) {
    int e = blockIdx.x * blockDim.x + threadIdx.x;
    if (e >= N_EDGES) return;
    int s;
    if (g_is64) s = (int)__ldg((const long long*)ei + e);
    else        s = __ldg((const int*)ei + e);
    atomicAdd(&g_cnt[s], 1);
}

// ---------------- pass 3a: per-block exclusive scan ----------------
__global__ __launch_bounds__(SCAN_BLK) void scan1_kernel() {
    __shared__ int sbuf[2][SCAN_BLK];
    int tid = threadIdx.x;
    int n = blockIdx.x * SCAN_BLK + tid;
    int c = g_cnt[n];                          // padded region is zeroed
    sbuf[0][tid] = c;
    __syncthreads();
    int cur = 0;
    #pragma unroll
    for (int off = 1; off < SCAN_BLK; off <<= 1) {
        int v = sbuf[cur][tid];
        if (tid >= off) v += sbuf[cur][tid - off];
        sbuf[cur ^ 1][tid] = v;
        cur ^= 1;
        __syncthreads();
    }
    int incl = sbuf[cur][tid];
    if (n < N_NODES) g_start[n] = incl - c;     // exclusive, block-local
    if (tid == SCAN_BLK - 1) g_bsum[blockIdx.x] = incl;
}

// ---------------- pass 3b: scan of block sums (tiny) ----------------
__global__ void scan2_kernel() {
    __shared__ int sb[SCAN_NBLK];
    int tid = threadIdx.x;
    if (tid < SCAN_NBLK) sb[tid] = g_bsum[tid];
    __syncthreads();
    if (tid == 0) {
        int run = 0;
        for (int b = 0; b < SCAN_NBLK; b++) { int t = sb[b]; sb[b] = run; run += t; }
    }
    __syncthreads();
    if (tid < SCAN_NBLK) g_bsum[tid] = sb[tid];
}

// ---------------- pass 3c: add block offsets, init cursors ----------------
__global__ __launch_bounds__(SCAN_BLK) void scan3_kernel() {
    int n = blockIdx.x * SCAN_BLK + threadIdx.x;
    if (n < N_NODES) {
        int st = g_start[n] + g_bsum[blockIdx.x];
        g_start[n] = st;
        g_cursor[n] = st;
    }
    if (n == 0) g_start[N_NODES] = N_EDGES;
}

// ---------------- pass 4: scatter edges into CSR buckets ----------------
__global__ __launch_bounds__(256) void scatter_kernel(const void* __restrict__ ei) {
    int e = blockIdx.x * blockDim.x + threadIdx.x;
    if (e >= N_EDGES) return;
    int s, d;
    if (g_is64) {
        const long long* p = (const long long*)ei;
        s = (int)__ldg(p + e);
        d = (int)__ldg(p + N_EDGES + e);
    } else {
        const int* p = (const int*)ei;
        s = __ldg(p + e);
        d = __ldg(p + N_EDGES + e);
    }
    int pos = atomicAdd(&g_cursor[s], 1);
    g_dst[pos] = d;
}

// ---------------- pass 5: per-node aggregation (atomic-free) ----------------
// One warp per node. Lane l owns output floats {2l, 2l+1}; head = l>>3.
__global__ __launch_bounds__(256) void agg_kernel(float* __restrict__ out) {
    int gw = (blockIdx.x * 256 + threadIdx.x) >> 5;   // warp id == node id
    if (gw >= N_NODES) return;
    int lane = threadIdx.x & 31;
    int n = gw;
    int hh = lane >> 3;

    float a_n = __ldg(&g_asrc[n * NH + hh]);
    int beg = g_start[n], end = g_start[n + 1];

    float2 acc = make_float2(0.f, 0.f);
    float dsum = 0.f;

    for (int base = beg; base < end; base += 32) {
        int m = end - base; if (m > 32) m = 32;
        int d_l = (base + lane < end) ? __ldg(&g_dst[base + lane]) : 0;
        #pragma unroll 4
        for (int i = 0; i < m; i++) {
            int d = __shfl_sync(0xffffffffu, d_l, i);
            float lg = a_n + __ldg(&g_adst[d * NH + hh]);
            lg = lg > 0.f ? lg : 0.2f * lg;            // leaky_relu(0.2)
            float ex = __expf(lg);                     // shift-free softmax (|lg|<~1.5)
            float2 v = __ldg(reinterpret_cast<const float2*>(
                                 &g_h[(size_t)d * HD]) + lane);
            acc.x += ex * v.x;
            acc.y += ex * v.y;
            dsum  += ex;
        }
    }

    float inv = 1.f / (dsum + 1e-16f);
    reinterpret_cast<float2*>(out + (size_t)n * HD)[lane] =
        make_float2(acc.x * inv, acc.y * inv);
}

// ---------------- launch ----------------
extern "C" void kernel_launch(void* const* d_in, const int* in_sizes, int n_in,
                              void* d_out, int out_size) {
    const float* x     = (const float*)d_in[0];
    const void*  ei    = d_in[1];
    const float* W_lin = (const float*)d_in[2];
    const float* W_att = (const float*)d_in[3];
    float* out = (float*)d_out;

    pass0_kernel<<<(SCAN_NBLK * SCAN_BLK + 255) / 256, 256>>>((const int*)ei);
    node_kernel<<<N_NODES / 32, 256>>>(x, W_lin, W_att);
    count_kernel<<<(N_EDGES + 255) / 256, 256>>>(ei);
    scan1_kernel<<<SCAN_NBLK, SCAN_BLK>>>();
    scan2_kernel<<<1, 128>>>();
    scan3_kernel<<<SCAN_NBLK, SCAN_BLK>>>();
    scatter_kernel<<<(N_EDGES + 255) / 256, 256>>>(ei);
    agg_kernel<<<(N_NODES * 32 + 255) / 256, 256>>>(out);
}